// round 15
// baseline (speedup 1.0000x reference)
#include <cuda_runtime.h>
#include <cuda_fp16.h>
#include <cstdint>
#include <cstddef>

// ---------------------------------------------------------------------------
// LatentAttention v12: B=2, T=2048, n_embd=1024, heads=16, latent=64
//   - ALL GEMMs single fp16 MMA/step (q residual dropped; budget-verified)
//   - build_wqc writes W_qc directly as fp16 [N][K] (no fp32 intermediate)
//   - GEMM: 2-array stages, 3-stage cp.async pipeline, ldmatrix
//   - flash: single fp16 MMA QK^T/PV, fp32 softmax, register prefetch
//   error budget: sqrt(6.25^2 + 2.4^2) ~ 6.7e-4  (gate 1e-3)
// ---------------------------------------------------------------------------

#define N_EMBD   1024
#define N_HEADS  16
#define LATENT   64
#define BATCH    2
#define SEQ      2048
#define MROWS    (BATCH * SEQ)          // 4096
#define KDIM     1024

// ------------------------- device scratch ----------------------------------
__device__ float  g_bqc[N_EMBD];
__device__ __half g_qkv[3 * MROWS * N_EMBD];    // [qc | k | v] fp16
__device__ __half g_x  [MROWS * N_EMBD];        // x fp16
__device__ __half g_ys [MROWS * N_EMBD];        // y fp16
__device__ __half g_wt[4][N_EMBD * N_EMBD];     // 0=Wqc 1=Wk 2=Wv 3=Wo, [N][K]

// ---------------------------------------------------------------------------
// Wqc fused build: g_wt[0][col][c] = fp16( sum_d Wq[c, h*64+d] * Wc[d, l] )
// (col = h*64+l).  Thread map: c varies fastest -> coalesced fp16 writes.
// Also bqc[col] (computed by the c==0 thread of each col).
// ---------------------------------------------------------------------------
__global__ void build_wqc_t(const float* __restrict__ Wq,
                            const float* __restrict__ Wc,
                            const float* __restrict__ bq,
                            __half* __restrict__ Wt,
                            float* __restrict__ bqc)
{
    const int idx = blockIdx.x * blockDim.x + threadIdx.x;
    const int c   = idx & 1023;
    const int col = idx >> 10;
    const int h   = col >> 6;
    const int l   = col & 63;
    const float* wrow = &Wq[(size_t)c * N_EMBD + h * LATENT];
    float s = 0.f;
#pragma unroll 8
    for (int d = 0; d < LATENT; d++)
        s += wrow[d] * Wc[d * LATENT + l];
    Wt[(size_t)col * KDIM + c] = __float2half_rn(s);
    if (c == 0) {
        float sb = 0.f;
#pragma unroll 8
        for (int d = 0; d < LATENT; d++)
            sb += bq[h * LATENT + d] * Wc[d * LATENT + l];
        bqc[col] = sb;
    }
}

// fp32 -> fp16 convert (2 elems / thread)
__global__ void xcvt(const float* __restrict__ src, __half2* __restrict__ dst,
                     int n2)
{
    int i = blockIdx.x * blockDim.x + threadIdx.x;
    if (i >= n2) return;
    const float2 v = reinterpret_cast<const float2*>(src)[i];
    dst[i] = __floats2half2_rn(v.x, v.y);
}

// transpose Wk/Wv/Wo to [N][K] fp16 (grid.z = 0..2 -> g_wt[1..3])
__global__ void tsplit3(const float* __restrict__ W1,
                        const float* __restrict__ W2,
                        const float* __restrict__ W3,
                        __half* __restrict__ T)
{
    __shared__ float t[32][33];
    const int z = blockIdx.z;
    const float* W = (z == 0) ? W1 : (z == 1) ? W2 : W3;
    __half* th = T + (size_t)(z + 1) * N_EMBD * N_EMBD;

    const int tx = threadIdx.x, ty = threadIdx.y;
    const int n0 = blockIdx.x * 32, k0 = blockIdx.y * 32;
#pragma unroll
    for (int i = 0; i < 4; i++)
        t[ty + 8 * i][tx] = W[(size_t)(k0 + ty + 8 * i) * N_EMBD + n0 + tx];
    __syncthreads();
#pragma unroll
    for (int i = 0; i < 4; i++) {
        const int n = n0 + ty + 8 * i;
        const int k = k0 + tx;
        th[(size_t)n * KDIM + k] = __float2half_rn(t[tx][ty + 8 * i]);
    }
}

// ---------------------------------------------------------------------------
// primitives
// ---------------------------------------------------------------------------
__device__ __forceinline__
void mma_f16(float& d0, float& d1, float& d2, float& d3,
             uint32_t a0, uint32_t a1, uint32_t a2, uint32_t a3,
             uint32_t b0, uint32_t b1)
{
    asm volatile(
        "mma.sync.aligned.m16n8k16.row.col.f32.f16.f16.f32 "
        "{%0,%1,%2,%3}, {%4,%5,%6,%7}, {%8,%9}, {%0,%1,%2,%3};\n"
        : "+f"(d0), "+f"(d1), "+f"(d2), "+f"(d3)
        : "r"(a0), "r"(a1), "r"(a2), "r"(a3), "r"(b0), "r"(b1));
}

__device__ __forceinline__ uint32_t pack_h(float x, float y)
{
    __half2 h = __floats2half2_rn(x, y);
    return *reinterpret_cast<uint32_t*>(&h);
}

__device__ __forceinline__ uint32_t mul8h(uint32_t w)
{
    __half2 v = *reinterpret_cast<__half2*>(&w);
    v = __hmul2(v, __floats2half2_rn(0.125f, 0.125f));   // 2^-3 exact
    return *reinterpret_cast<uint32_t*>(&v);
}

__device__ __forceinline__ void cp16(uint32_t d, const void* s) {
    asm volatile("cp.async.cg.shared.global [%0], [%1], 16;" :: "r"(d), "l"(s));
}
__device__ __forceinline__ void cp_commit() {
    asm volatile("cp.async.commit_group;");
}
__device__ __forceinline__ void cp_wait1() {
    asm volatile("cp.async.wait_group 1;");
}
__device__ __forceinline__
void ldsm4(uint32_t& r0, uint32_t& r1, uint32_t& r2, uint32_t& r3, uint32_t a) {
    asm volatile("ldmatrix.sync.aligned.m8n8.x4.shared.b16 {%0,%1,%2,%3}, [%4];"
                 : "=r"(r0), "=r"(r1), "=r"(r2), "=r"(r3) : "r"(a));
}

// ---------------------------------------------------------------------------
// GEMM (single fp16 term): 128x128 tile, BK=32, 8 warps (2m x 4n),
// 3-stage cp.async pipeline (2 arrays/stage), ldmatrix frags, 2 CTAs/SM.
// ---------------------------------------------------------------------------
#define SMW 20
#define TST (128 * SMW)            // words per array (10240 B)
#define TSTG (2 * TST)             // words per stage (A, B)
#define NST 3
#define GEMM_SMEM (NST * TSTG * 4) // 61440 bytes

template<bool HALF_OUT>
__device__ __forceinline__
void gemm1_body(const __half* __restrict__ A_, const __half* __restrict__ B_,
                const float* __restrict__ bias,
                float* __restrict__ C, __half* __restrict__ Ch,
                int N, int K, int bx, int by)
{
    extern __shared__ uint32_t gsm[];
    const int tid    = threadIdx.x;
    const int lane   = tid & 31;
    const int wid    = tid >> 5;
    const int warp_m = wid >> 2;
    const int warp_n = wid & 3;
    const int m0     = by * 128;
    const int n0     = bx * 128;
    const int lg     = lane >> 2;
    const int lc     = lane & 3;
    const uint32_t sbase = (uint32_t)__cvta_generic_to_shared(gsm);

    float acc[4][4][4];
#pragma unroll
    for (int i = 0; i < 4; i++)
#pragma unroll
        for (int j = 0; j < 4; j++)
#pragma unroll
            for (int c = 0; c < 4; c++) acc[i][j][c] = 0.f;

    const int KT = K >> 5;               // 32

    auto load_stage = [&](int slot, int kb) {
        const uint32_t dst0 = sbase + (uint32_t)(slot * TSTG * 4);
#pragma unroll
        for (int arr = 0; arr < 2; arr++) {
            const __half* src = (arr == 0) ? A_ : B_;
            const int rbase = (arr == 0) ? m0 : n0;
#pragma unroll
            for (int it = 0; it < 2; it++) {
                const int sub = tid + it * 256;      // 0..511
                const int row = sub >> 2;            // 0..127
                const int q   = sub & 3;             // 16B chunk
                cp16(dst0 + (uint32_t)((arr * TST + row * SMW + q * 4) * 4),
                     src + (size_t)(rbase + row) * K + kb + q * 8);
            }
        }
        cp_commit();
    };

    load_stage(0, 0);
    load_stage(1, 32);

    const int arow = lane & 15;
    const int acol = (lane & 16) ? 4 : 0;
    const int brow = (lane & 7) + ((lane & 16) ? 8 : 0);
    const int bcol = (lane & 8) ? 4 : 0;

    for (int kt = 0; kt < KT; kt++) {
        cp_wait1();                       // stage kt resident
        __syncthreads();                  // slot (kt-1)%3 compute finished
        if (kt + 2 < KT) load_stage((kt + 2) % NST, (kt + 2) * 32);
        else             cp_commit();     // keep group accounting exact

        const int slot = kt % NST;
        const uint32_t st   = sbase + (uint32_t)(slot * TSTG * 4);
        const uint32_t offA = st;
        const uint32_t offB = st + TST * 4;

#pragma unroll
        for (int ks = 0; ks < 2; ks++) {
            const int kw = ks * 8;
            uint32_t bh[8];
#pragma unroll
            for (int jp = 0; jp < 2; jp++) {
                const int rB = warp_n * 32 + jp * 16 + brow;
                const uint32_t off = (uint32_t)((rB * SMW + kw + bcol) * 4);
                ldsm4(bh[jp*4+0], bh[jp*4+1], bh[jp*4+2], bh[jp*4+3], offB + off);
            }
#pragma unroll
            for (int i = 0; i < 4; i++) {
                const int rA = warp_m * 64 + i * 16 + arow;
                const uint32_t off = (uint32_t)((rA * SMW + kw + acol) * 4);
                uint32_t a0, a1, a2, a3;
                ldsm4(a0, a1, a2, a3, offA + off);
#pragma unroll
                for (int j = 0; j < 4; j++) {
                    const int bi = (j >> 1) * 4 + (j & 1) * 2;
                    float* d = acc[i][j];
                    mma_f16(d[0], d[1], d[2], d[3],
                            a0, a1, a2, a3, bh[bi], bh[bi+1]);
                }
            }
        }
    }

    // epilogue
#pragma unroll
    for (int j = 0; j < 4; j++) {
        const int cn = n0 + warp_n * 32 + j * 8 + 2 * lc;
        const float2 bb = *reinterpret_cast<const float2*>(&bias[cn]);
#pragma unroll
        for (int i = 0; i < 4; i++) {
            const int r = m0 + warp_m * 64 + i * 16 + lg;
            const float v0 = acc[i][j][0] + bb.x, v1 = acc[i][j][1] + bb.y;
            const float v2 = acc[i][j][2] + bb.x, v3 = acc[i][j][3] + bb.y;
            if (HALF_OUT) {
                *reinterpret_cast<uint32_t*>(Ch + (size_t)r * N + cn) =
                    pack_h(v0, v1);
                *reinterpret_cast<uint32_t*>(Ch + (size_t)(r + 8) * N + cn) =
                    pack_h(v2, v3);
            } else {
                *reinterpret_cast<float2*>(&C[(size_t)r * N + cn]) =
                    make_float2(v0, v1);
                *reinterpret_cast<float2*>(&C[(size_t)(r + 8) * N + cn]) =
                    make_float2(v2, v3);
            }
        }
    }
}

__global__ __launch_bounds__(256, 2)
void gemm_qkv_mma(const __half* __restrict__ x,
                  const float* __restrict__ bqc,
                  const float* __restrict__ bk,
                  const float* __restrict__ bv,
                  __half* __restrict__ qkv)
{
    const int z = blockIdx.z;
    const float* b = (z == 0) ? bqc : (z == 1) ? bk : bv;
    gemm1_body<true>(x, g_wt[z], b, nullptr,
                     qkv + (size_t)z * MROWS * N_EMBD,
                     N_EMBD, KDIM, blockIdx.x, blockIdx.y);
}

__global__ __launch_bounds__(256, 2)
void gemm_out_mma(const __half* __restrict__ y,
                  const float* __restrict__ bo, float* __restrict__ C)
{
    gemm1_body<false>(y, g_wt[3], bo, C, nullptr,
                      N_EMBD, KDIM, blockIdx.x, blockIdx.y);
}

// ---------------------------------------------------------------------------
// Flash attention (unchanged from v11): single fp16 MMA QK^T/PV,
// fp32 softmax, register-prefetched K/V tiles.
// ---------------------------------------------------------------------------
#define FW 36

__global__ __launch_bounds__(256)
void flash_mma(const __half* __restrict__ Qg,
               const __half* __restrict__ Kg, const __half* __restrict__ Vg,
               __half* __restrict__ Yg)
{
    __shared__ uint32_t sK[64][FW];   // [key][lat-pair]
    __shared__ uint32_t sV[64][FW];   // [lat][key-pair] (transposed)

    const int tid  = threadIdx.x;
    const int lane = tid & 31;
    const int wid  = tid >> 5;
    const int g    = lane >> 2;
    const int c    = lane & 3;
    const int qb   = gridDim.x - 1 - blockIdx.x;   // long blocks first
    const int bh   = blockIdx.y;
    const int b    = bh >> 4;
    const int h    = bh & 15;
    const size_t base = (size_t)b * SEQ * N_EMBD + (size_t)h * LATENT;

    const int r0 = qb * 128 + wid * 16 + g;
    const int r1 = r0 + 8;

    int lkey[4], lwq[4];
#pragma unroll
    for (int it = 0; it < 4; it++) {
        const int idx = tid + it * 256;
        lkey[it] = idx >> 4;
        lwq[it]  = idx & 15;
    }

    auto store_tile = [&](const uint2* kvr, const uint2* vvr) {
#pragma unroll
        for (int it = 0; it < 4; it++) {
            *reinterpret_cast<uint2*>(&sK[lkey[it]][lwq[it] * 2]) = kvr[it];
            const __half* ve = reinterpret_cast<const __half*>(&vvr[it]);
            __half* vp = reinterpret_cast<__half*>(&sV[0][0]);
#pragma unroll
            for (int e = 0; e < 4; e++)
                vp[(lwq[it] * 4 + e) * (2 * FW) + lkey[it]] = ve[e];
        }
    };

    uint32_t qf[4][4];
#pragma unroll
    for (int ks = 0; ks < 4; ks++) {
        const int k0a = 16 * ks + 2 * c;
        const size_t e0 = base + (size_t)r0 * N_EMBD + k0a;
        const size_t e1 = base + (size_t)r1 * N_EMBD + k0a;
        qf[ks][0] = mul8h(*reinterpret_cast<const uint32_t*>(Qg + e0));
        qf[ks][1] = mul8h(*reinterpret_cast<const uint32_t*>(Qg + e1));
        qf[ks][2] = mul8h(*reinterpret_cast<const uint32_t*>(Qg + e0 + 8));
        qf[ks][3] = mul8h(*reinterpret_cast<const uint32_t*>(Qg + e1 + 8));
    }

    // preload tile 0
    {
        uint2 kvr[4], vvr[4];
#pragma unroll
        for (int it = 0; it < 4; it++) {
            const size_t ge = base + (size_t)lkey[it] * N_EMBD + lwq[it] * 4;
            kvr[it] = *reinterpret_cast<const uint2*>(Kg + ge);
            vvr[it] = *reinterpret_cast<const uint2*>(Vg + ge);
        }
        store_tile(kvr, vvr);
    }
    __syncthreads();

    float m0 = -1e30f, m1 = -1e30f, l0 = 0.f, l1 = 0.f;
    float O[8][4];
#pragma unroll
    for (int j = 0; j < 8; j++)
#pragma unroll
        for (int t = 0; t < 4; t++) O[j][t] = 0.f;

    const int jmax = 2 * qb + 1;
    for (int jb = 0; jb <= jmax; jb++) {
        uint2 kvr[4], vvr[4];
        const bool has_next = (jb < jmax);
        if (has_next) {
#pragma unroll
            for (int it = 0; it < 4; it++) {
                const size_t ge = base +
                    (size_t)((jb + 1) * 64 + lkey[it]) * N_EMBD + lwq[it] * 4;
                kvr[it] = *reinterpret_cast<const uint2*>(Kg + ge);
                vvr[it] = *reinterpret_cast<const uint2*>(Vg + ge);
            }
        }

        float S[8][4];
#pragma unroll
        for (int j = 0; j < 8; j++)
#pragma unroll
            for (int t = 0; t < 4; t++) S[j][t] = 0.f;

#pragma unroll
        for (int ks = 0; ks < 4; ks++) {
#pragma unroll
            for (int j = 0; j < 8; j++) {
                const int key = 8 * j + g;
                const uint32_t b0 = sK[key][8 * ks + c];
                const uint32_t b1 = sK[key][8 * ks + 4 + c];
                mma_f16(S[j][0], S[j][1], S[j][2], S[j][3],
                        qf[ks][0], qf[ks][1], qf[ks][2], qf[ks][3], b0, b1);
            }
        }

        if (jb >= 2 * qb) {
#pragma unroll
            for (int j = 0; j < 8; j++) {
                const int col = jb * 64 + 8 * j + 2 * c;
                if (col     > r0) S[j][0] = -1e30f;
                if (col + 1 > r0) S[j][1] = -1e30f;
                if (col     > r1) S[j][2] = -1e30f;
                if (col + 1 > r1) S[j][3] = -1e30f;
            }
        }

        float mx0 = -1e30f, mx1 = -1e30f;
#pragma unroll
        for (int j = 0; j < 8; j++) {
            mx0 = fmaxf(mx0, fmaxf(S[j][0], S[j][1]));
            mx1 = fmaxf(mx1, fmaxf(S[j][2], S[j][3]));
        }
        mx0 = fmaxf(mx0, __shfl_xor_sync(0xffffffffu, mx0, 1));
        mx0 = fmaxf(mx0, __shfl_xor_sync(0xffffffffu, mx0, 2));
        mx1 = fmaxf(mx1, __shfl_xor_sync(0xffffffffu, mx1, 1));
        mx1 = fmaxf(mx1, __shfl_xor_sync(0xffffffffu, mx1, 2));

        const float mn0 = fmaxf(m0, mx0);
        const float mn1 = fmaxf(m1, mx1);
        const float a0  = __expf(m0 - mn0);
        const float a1  = __expf(m1 - mn1);
        m0 = mn0; m1 = mn1;

        float rs0 = 0.f, rs1 = 0.f;
#pragma unroll
        for (int j = 0; j < 8; j++) {
            S[j][0] = __expf(S[j][0] - mn0);
            S[j][1] = __expf(S[j][1] - mn0);
            S[j][2] = __expf(S[j][2] - mn1);
            S[j][3] = __expf(S[j][3] - mn1);
            rs0 += S[j][0] + S[j][1];
            rs1 += S[j][2] + S[j][3];
        }
        rs0 += __shfl_xor_sync(0xffffffffu, rs0, 1);
        rs0 += __shfl_xor_sync(0xffffffffu, rs0, 2);
        rs1 += __shfl_xor_sync(0xffffffffu, rs1, 1);
        rs1 += __shfl_xor_sync(0xffffffffu, rs1, 2);
        l0 = l0 * a0 + rs0;
        l1 = l1 * a1 + rs1;

#pragma unroll
        for (int j = 0; j < 8; j++) {
            O[j][0] *= a0; O[j][1] *= a0;
            O[j][2] *= a1; O[j][3] *= a1;
        }

#pragma unroll
        for (int t = 0; t < 4; t++) {
            const uint32_t p0 = pack_h(S[2 * t][0],     S[2 * t][1]);
            const uint32_t p1 = pack_h(S[2 * t][2],     S[2 * t][3]);
            const uint32_t p2 = pack_h(S[2 * t + 1][0], S[2 * t + 1][1]);
            const uint32_t p3 = pack_h(S[2 * t + 1][2], S[2 * t + 1][3]);
#pragma unroll
            for (int j = 0; j < 8; j++) {
                const int lat = 8 * j + g;
                const uint32_t b0 = sV[lat][8 * t + c];
                const uint32_t b1 = sV[lat][8 * t + 4 + c];
                mma_f16(O[j][0], O[j][1], O[j][2], O[j][3], p0, p1, p2, p3, b0, b1);
            }
        }

        if (has_next) {
            __syncthreads();
            store_tile(kvr, vvr);
            __syncthreads();
        }
    }

    const float i0 = 1.f / l0;
    const float i1 = 1.f / l1;
#pragma unroll
    for (int j = 0; j < 8; j++) {
        const int col = 8 * j + 2 * c;
        *reinterpret_cast<uint32_t*>(Yg + base + (size_t)r0 * N_EMBD + col) =
            pack_h(O[j][0] * i0, O[j][1] * i0);
        *reinterpret_cast<uint32_t*>(Yg + base + (size_t)r1 * N_EMBD + col) =
            pack_h(O[j][2] * i1, O[j][3] * i1);
    }
}

// ---------------------------------------------------------------------------
// Launcher. Inputs: x,Wq,bq,Wk,bk,Wv,bv,Wo,bo,Wc   (6 launches total)
// ---------------------------------------------------------------------------
extern "C" void kernel_launch(void* const* d_in, const int* in_sizes, int n_in,
                              void* d_out, int out_size)
{
    const float* x  = (const float*)d_in[0];
    const float* Wq = (const float*)d_in[1];
    const float* bq = (const float*)d_in[2];
    const float* Wk = (const float*)d_in[3];
    const float* bk = (const float*)d_in[4];
    const float* Wv = (const float*)d_in[5];
    const float* bv = (const float*)d_in[6];
    const float* Wo = (const float*)d_in[7];
    const float* bo = (const float*)d_in[8];
    const float* Wc = (const float*)d_in[9];
    float* out = (float*)d_out;

    float* pbqc;
    __half *pqkv, *px16, *pys, *pwt;
    cudaGetSymbolAddress((void**)&pbqc, g_bqc);
    cudaGetSymbolAddress((void**)&pqkv, g_qkv);
    cudaGetSymbolAddress((void**)&px16, g_x);
    cudaGetSymbolAddress((void**)&pys,  g_ys);
    cudaGetSymbolAddress((void**)&pwt,  g_wt);

    const size_t MN = (size_t)MROWS * N_EMBD;

    cudaFuncSetAttribute(gemm_qkv_mma,
                         cudaFuncAttributeMaxDynamicSharedMemorySize, GEMM_SMEM);
    cudaFuncSetAttribute(gemm_out_mma,
                         cudaFuncAttributeMaxDynamicSharedMemorySize, GEMM_SMEM);

    // 1. Wqc build (writes g_wt[0] fp16 [N][K] directly)
    build_wqc_t<<<4096, 256>>>(Wq, Wc, bq, pwt, pbqc);

    // 2. convert x to fp16
    const int n2x = MROWS * N_EMBD / 2;
    xcvt<<<(n2x + 255) / 256, 256>>>(x, (__half2*)px16, n2x);

    // 3. transpose Wk/Wv/Wo to [N][K] fp16
    const dim3 tg(N_EMBD / 32, N_EMBD / 32, 3);
    tsplit3<<<tg, dim3(32, 8)>>>(Wk, Wv, Wo, pwt);

    // 4. QKV projection (all single-term fp16)
    const dim3 gq(N_EMBD / 128, MROWS / 128, 3);
    gemm_qkv_mma<<<gq, 256, GEMM_SMEM>>>(px16, pbqc, bk, bv, pqkv);

    // 5. attention
    flash_mma<<<dim3(SEQ / 128, BATCH * N_HEADS), 256>>>(
        pqkv, pqkv + MN, pqkv + 2 * MN, pys);

    // 6. output projection
    const dim3 gg(N_EMBD / 128, MROWS / 128);
    gemm_out_mma<<<gg, 256, GEMM_SMEM>>>(pys, bo, out);
}

// round 16
// speedup vs baseline: 1.6845x; 1.6845x over previous
#include <cuda_runtime.h>
#include <cuda_fp16.h>
#include <cstdint>
#include <cstddef>

// ---------------------------------------------------------------------------
// LatentAttention v13: B=2, T=2048, n_embd=1024, heads=16, latent=64
//   = v12 compute (all GEMMs single fp16 MMA/step; flash 1-MMA QK/PV)
//   + v11 prep structure restored (coalesced build_wqc -> fp32, tiled
//     transpose to fp16) — v12's fused build had stride-4KB Wq reads.
// ---------------------------------------------------------------------------

#define N_EMBD   1024
#define N_HEADS  16
#define LATENT   64
#define BATCH    2
#define SEQ      2048
#define MROWS    (BATCH * SEQ)          // 4096
#define KDIM     1024

// ------------------------- device scratch ----------------------------------
__device__ float  g_Wqc[N_EMBD * N_EMBD];
__device__ float  g_bqc[N_EMBD];
__device__ __half g_qkv[3 * MROWS * N_EMBD];    // [qc | k | v] fp16
__device__ __half g_x  [MROWS * N_EMBD];        // x fp16
__device__ __half g_ys [MROWS * N_EMBD];        // y fp16
__device__ __half g_wt[4][N_EMBD * N_EMBD];     // 0=Wqc 1=Wk 2=Wv 3=Wo, [N][K]

// ---------------------------------------------------------------------------
// Wqc[c, h*64+l] = sum_d Wq[c, h*64+d] * Wc[d, l]   (coalesced: col fastest)
// ---------------------------------------------------------------------------
__global__ void build_wqc(const float* __restrict__ Wq,
                          const float* __restrict__ Wc,
                          const float* __restrict__ bq,
                          float* __restrict__ Wqc,
                          float* __restrict__ bqc)
{
    int idx = blockIdx.x * blockDim.x + threadIdx.x;
    int c   = idx >> 10;
    int col = idx & 1023;
    int h   = col >> 6;
    int l   = col & 63;
    const float* wrow = &Wq[(size_t)c * N_EMBD + h * LATENT];
    float s = 0.f;
#pragma unroll 8
    for (int d = 0; d < LATENT; d++)
        s += wrow[d] * Wc[d * LATENT + l];
    Wqc[idx] = s;
    if (c == 0) {
        float sb = 0.f;
#pragma unroll 8
        for (int d = 0; d < LATENT; d++)
            sb += bq[h * LATENT + d] * Wc[d * LATENT + l];
        bqc[col] = sb;
    }
}

// fp32 -> fp16 convert (2 elems / thread)
__global__ void xcvt(const float* __restrict__ src, __half2* __restrict__ dst,
                     int n2)
{
    int i = blockIdx.x * blockDim.x + threadIdx.x;
    if (i >= n2) return;
    const float2 v = reinterpret_cast<const float2*>(src)[i];
    dst[i] = __floats2half2_rn(v.x, v.y);
}

// transpose all 4 weight matrices to [N][K] fp16 (tiled, coalesced)
__global__ void tsplit_all(const float* __restrict__ W0,
                           const float* __restrict__ W1,
                           const float* __restrict__ W2,
                           const float* __restrict__ W3,
                           __half* __restrict__ T)
{
    __shared__ float t[32][33];
    const int z = blockIdx.z;
    const float* W = (z == 0) ? W0 : (z == 1) ? W1 : (z == 2) ? W2 : W3;
    __half* th = T + (size_t)z * N_EMBD * N_EMBD;

    const int tx = threadIdx.x, ty = threadIdx.y;
    const int n0 = blockIdx.x * 32, k0 = blockIdx.y * 32;
#pragma unroll
    for (int i = 0; i < 4; i++)
        t[ty + 8 * i][tx] = W[(size_t)(k0 + ty + 8 * i) * N_EMBD + n0 + tx];
    __syncthreads();
#pragma unroll
    for (int i = 0; i < 4; i++) {
        const int n = n0 + ty + 8 * i;
        const int k = k0 + tx;
        th[(size_t)n * KDIM + k] = __float2half_rn(t[tx][ty + 8 * i]);
    }
}

// ---------------------------------------------------------------------------
// primitives
// ---------------------------------------------------------------------------
__device__ __forceinline__
void mma_f16(float& d0, float& d1, float& d2, float& d3,
             uint32_t a0, uint32_t a1, uint32_t a2, uint32_t a3,
             uint32_t b0, uint32_t b1)
{
    asm volatile(
        "mma.sync.aligned.m16n8k16.row.col.f32.f16.f16.f32 "
        "{%0,%1,%2,%3}, {%4,%5,%6,%7}, {%8,%9}, {%0,%1,%2,%3};\n"
        : "+f"(d0), "+f"(d1), "+f"(d2), "+f"(d3)
        : "r"(a0), "r"(a1), "r"(a2), "r"(a3), "r"(b0), "r"(b1));
}

__device__ __forceinline__ uint32_t pack_h(float x, float y)
{
    __half2 h = __floats2half2_rn(x, y);
    return *reinterpret_cast<uint32_t*>(&h);
}

__device__ __forceinline__ uint32_t mul8h(uint32_t w)
{
    __half2 v = *reinterpret_cast<__half2*>(&w);
    v = __hmul2(v, __floats2half2_rn(0.125f, 0.125f));   // 2^-3 exact
    return *reinterpret_cast<uint32_t*>(&v);
}

__device__ __forceinline__ void cp16(uint32_t d, const void* s) {
    asm volatile("cp.async.cg.shared.global [%0], [%1], 16;" :: "r"(d), "l"(s));
}
__device__ __forceinline__ void cp_commit() {
    asm volatile("cp.async.commit_group;");
}
__device__ __forceinline__ void cp_wait1() {
    asm volatile("cp.async.wait_group 1;");
}
__device__ __forceinline__
void ldsm4(uint32_t& r0, uint32_t& r1, uint32_t& r2, uint32_t& r3, uint32_t a) {
    asm volatile("ldmatrix.sync.aligned.m8n8.x4.shared.b16 {%0,%1,%2,%3}, [%4];"
                 : "=r"(r0), "=r"(r1), "=r"(r2), "=r"(r3) : "r"(a));
}

// ---------------------------------------------------------------------------
// GEMM (single fp16 term): 128x128 tile, BK=32, 8 warps (2m x 4n),
// 3-stage cp.async pipeline (2 arrays/stage), ldmatrix frags.
// ---------------------------------------------------------------------------
#define SMW 20
#define TST (128 * SMW)            // words per array (10240 B)
#define TSTG (2 * TST)             // words per stage (A, B)
#define NST 3
#define GEMM_SMEM (NST * TSTG * 4) // 61440 bytes

template<bool HALF_OUT>
__device__ __forceinline__
void gemm1_body(const __half* __restrict__ A_, const __half* __restrict__ B_,
                const float* __restrict__ bias,
                float* __restrict__ C, __half* __restrict__ Ch,
                int N, int K, int bx, int by)
{
    extern __shared__ uint32_t gsm[];
    const int tid    = threadIdx.x;
    const int lane   = tid & 31;
    const int wid    = tid >> 5;
    const int warp_m = wid >> 2;
    const int warp_n = wid & 3;
    const int m0     = by * 128;
    const int n0     = bx * 128;
    const int lg     = lane >> 2;
    const int lc     = lane & 3;
    const uint32_t sbase = (uint32_t)__cvta_generic_to_shared(gsm);

    float acc[4][4][4];
#pragma unroll
    for (int i = 0; i < 4; i++)
#pragma unroll
        for (int j = 0; j < 4; j++)
#pragma unroll
            for (int c = 0; c < 4; c++) acc[i][j][c] = 0.f;

    const int KT = K >> 5;               // 32

    auto load_stage = [&](int slot, int kb) {
        const uint32_t dst0 = sbase + (uint32_t)(slot * TSTG * 4);
#pragma unroll
        for (int arr = 0; arr < 2; arr++) {
            const __half* src = (arr == 0) ? A_ : B_;
            const int rbase = (arr == 0) ? m0 : n0;
#pragma unroll
            for (int it = 0; it < 2; it++) {
                const int sub = tid + it * 256;      // 0..511
                const int row = sub >> 2;            // 0..127
                const int q   = sub & 3;             // 16B chunk
                cp16(dst0 + (uint32_t)((arr * TST + row * SMW + q * 4) * 4),
                     src + (size_t)(rbase + row) * K + kb + q * 8);
            }
        }
        cp_commit();
    };

    load_stage(0, 0);
    load_stage(1, 32);

    const int arow = lane & 15;
    const int acol = (lane & 16) ? 4 : 0;
    const int brow = (lane & 7) + ((lane & 16) ? 8 : 0);
    const int bcol = (lane & 8) ? 4 : 0;

    for (int kt = 0; kt < KT; kt++) {
        cp_wait1();                       // stage kt resident
        __syncthreads();                  // slot (kt-1)%3 compute finished
        if (kt + 2 < KT) load_stage((kt + 2) % NST, (kt + 2) * 32);
        else             cp_commit();     // keep group accounting exact

        const int slot = kt % NST;
        const uint32_t st   = sbase + (uint32_t)(slot * TSTG * 4);
        const uint32_t offA = st;
        const uint32_t offB = st + TST * 4;

#pragma unroll
        for (int ks = 0; ks < 2; ks++) {
            const int kw = ks * 8;
            uint32_t bh[8];
#pragma unroll
            for (int jp = 0; jp < 2; jp++) {
                const int rB = warp_n * 32 + jp * 16 + brow;
                const uint32_t off = (uint32_t)((rB * SMW + kw + bcol) * 4);
                ldsm4(bh[jp*4+0], bh[jp*4+1], bh[jp*4+2], bh[jp*4+3], offB + off);
            }
#pragma unroll
            for (int i = 0; i < 4; i++) {
                const int rA = warp_m * 64 + i * 16 + arow;
                const uint32_t off = (uint32_t)((rA * SMW + kw + acol) * 4);
                uint32_t a0, a1, a2, a3;
                ldsm4(a0, a1, a2, a3, offA + off);
#pragma unroll
                for (int j = 0; j < 4; j++) {
                    const int bi = (j >> 1) * 4 + (j & 1) * 2;
                    float* d = acc[i][j];
                    mma_f16(d[0], d[1], d[2], d[3],
                            a0, a1, a2, a3, bh[bi], bh[bi+1]);
                }
            }
        }
    }

    // epilogue
#pragma unroll
    for (int j = 0; j < 4; j++) {
        const int cn = n0 + warp_n * 32 + j * 8 + 2 * lc;
        const float2 bb = *reinterpret_cast<const float2*>(&bias[cn]);
#pragma unroll
        for (int i = 0; i < 4; i++) {
            const int r = m0 + warp_m * 64 + i * 16 + lg;
            const float v0 = acc[i][j][0] + bb.x, v1 = acc[i][j][1] + bb.y;
            const float v2 = acc[i][j][2] + bb.x, v3 = acc[i][j][3] + bb.y;
            if (HALF_OUT) {
                *reinterpret_cast<uint32_t*>(Ch + (size_t)r * N + cn) =
                    pack_h(v0, v1);
                *reinterpret_cast<uint32_t*>(Ch + (size_t)(r + 8) * N + cn) =
                    pack_h(v2, v3);
            } else {
                *reinterpret_cast<float2*>(&C[(size_t)r * N + cn]) =
                    make_float2(v0, v1);
                *reinterpret_cast<float2*>(&C[(size_t)(r + 8) * N + cn]) =
                    make_float2(v2, v3);
            }
        }
    }
}

__global__ __launch_bounds__(256, 2)
void gemm_qkv_mma(const __half* __restrict__ x,
                  const float* __restrict__ bqc,
                  const float* __restrict__ bk,
                  const float* __restrict__ bv,
                  __half* __restrict__ qkv)
{
    const int z = blockIdx.z;
    const float* b = (z == 0) ? bqc : (z == 1) ? bk : bv;
    gemm1_body<true>(x, g_wt[z], b, nullptr,
                     qkv + (size_t)z * MROWS * N_EMBD,
                     N_EMBD, KDIM, blockIdx.x, blockIdx.y);
}

__global__ __launch_bounds__(256, 2)
void gemm_out_mma(const __half* __restrict__ y,
                  const float* __restrict__ bo, float* __restrict__ C)
{
    gemm1_body<false>(y, g_wt[3], bo, C, nullptr,
                      N_EMBD, KDIM, blockIdx.x, blockIdx.y);
}

// ---------------------------------------------------------------------------
// Flash attention (unchanged): single fp16 MMA QK^T/PV, fp32 softmax,
// register-prefetched K/V tiles.
// ---------------------------------------------------------------------------
#define FW 36

__global__ __launch_bounds__(256)
void flash_mma(const __half* __restrict__ Qg,
               const __half* __restrict__ Kg, const __half* __restrict__ Vg,
               __half* __restrict__ Yg)
{
    __shared__ uint32_t sK[64][FW];   // [key][lat-pair]
    __shared__ uint32_t sV[64][FW];   // [lat][key-pair] (transposed)

    const int tid  = threadIdx.x;
    const int lane = tid & 31;
    const int wid  = tid >> 5;
    const int g    = lane >> 2;
    const int c    = lane & 3;
    const int qb   = gridDim.x - 1 - blockIdx.x;   // long blocks first
    const int bh   = blockIdx.y;
    const int b    = bh >> 4;
    const int h    = bh & 15;
    const size_t base = (size_t)b * SEQ * N_EMBD + (size_t)h * LATENT;

    const int r0 = qb * 128 + wid * 16 + g;
    const int r1 = r0 + 8;

    int lkey[4], lwq[4];
#pragma unroll
    for (int it = 0; it < 4; it++) {
        const int idx = tid + it * 256;
        lkey[it] = idx >> 4;
        lwq[it]  = idx & 15;
    }

    auto store_tile = [&](const uint2* kvr, const uint2* vvr) {
#pragma unroll
        for (int it = 0; it < 4; it++) {
            *reinterpret_cast<uint2*>(&sK[lkey[it]][lwq[it] * 2]) = kvr[it];
            const __half* ve = reinterpret_cast<const __half*>(&vvr[it]);
            __half* vp = reinterpret_cast<__half*>(&sV[0][0]);
#pragma unroll
            for (int e = 0; e < 4; e++)
                vp[(lwq[it] * 4 + e) * (2 * FW) + lkey[it]] = ve[e];
        }
    };

    uint32_t qf[4][4];
#pragma unroll
    for (int ks = 0; ks < 4; ks++) {
        const int k0a = 16 * ks + 2 * c;
        const size_t e0 = base + (size_t)r0 * N_EMBD + k0a;
        const size_t e1 = base + (size_t)r1 * N_EMBD + k0a;
        qf[ks][0] = mul8h(*reinterpret_cast<const uint32_t*>(Qg + e0));
        qf[ks][1] = mul8h(*reinterpret_cast<const uint32_t*>(Qg + e1));
        qf[ks][2] = mul8h(*reinterpret_cast<const uint32_t*>(Qg + e0 + 8));
        qf[ks][3] = mul8h(*reinterpret_cast<const uint32_t*>(Qg + e1 + 8));
    }

    // preload tile 0
    {
        uint2 kvr[4], vvr[4];
#pragma unroll
        for (int it = 0; it < 4; it++) {
            const size_t ge = base + (size_t)lkey[it] * N_EMBD + lwq[it] * 4;
            kvr[it] = *reinterpret_cast<const uint2*>(Kg + ge);
            vvr[it] = *reinterpret_cast<const uint2*>(Vg + ge);
        }
        store_tile(kvr, vvr);
    }
    __syncthreads();

    float m0 = -1e30f, m1 = -1e30f, l0 = 0.f, l1 = 0.f;
    float O[8][4];
#pragma unroll
    for (int j = 0; j < 8; j++)
#pragma unroll
        for (int t = 0; t < 4; t++) O[j][t] = 0.f;

    const int jmax = 2 * qb + 1;
    for (int jb = 0; jb <= jmax; jb++) {
        uint2 kvr[4], vvr[4];
        const bool has_next = (jb < jmax);
        if (has_next) {
#pragma unroll
            for (int it = 0; it < 4; it++) {
                const size_t ge = base +
                    (size_t)((jb + 1) * 64 + lkey[it]) * N_EMBD + lwq[it] * 4;
                kvr[it] = *reinterpret_cast<const uint2*>(Kg + ge);
                vvr[it] = *reinterpret_cast<const uint2*>(Vg + ge);
            }
        }

        float S[8][4];
#pragma unroll
        for (int j = 0; j < 8; j++)
#pragma unroll
            for (int t = 0; t < 4; t++) S[j][t] = 0.f;

#pragma unroll
        for (int ks = 0; ks < 4; ks++) {
#pragma unroll
            for (int j = 0; j < 8; j++) {
                const int key = 8 * j + g;
                const uint32_t b0 = sK[key][8 * ks + c];
                const uint32_t b1 = sK[key][8 * ks + 4 + c];
                mma_f16(S[j][0], S[j][1], S[j][2], S[j][3],
                        qf[ks][0], qf[ks][1], qf[ks][2], qf[ks][3], b0, b1);
            }
        }

        if (jb >= 2 * qb) {
#pragma unroll
            for (int j = 0; j < 8; j++) {
                const int col = jb * 64 + 8 * j + 2 * c;
                if (col     > r0) S[j][0] = -1e30f;
                if (col + 1 > r0) S[j][1] = -1e30f;
                if (col     > r1) S[j][2] = -1e30f;
                if (col + 1 > r1) S[j][3] = -1e30f;
            }
        }

        float mx0 = -1e30f, mx1 = -1e30f;
#pragma unroll
        for (int j = 0; j < 8; j++) {
            mx0 = fmaxf(mx0, fmaxf(S[j][0], S[j][1]));
            mx1 = fmaxf(mx1, fmaxf(S[j][2], S[j][3]));
        }
        mx0 = fmaxf(mx0, __shfl_xor_sync(0xffffffffu, mx0, 1));
        mx0 = fmaxf(mx0, __shfl_xor_sync(0xffffffffu, mx0, 2));
        mx1 = fmaxf(mx1, __shfl_xor_sync(0xffffffffu, mx1, 1));
        mx1 = fmaxf(mx1, __shfl_xor_sync(0xffffffffu, mx1, 2));

        const float mn0 = fmaxf(m0, mx0);
        const float mn1 = fmaxf(m1, mx1);
        const float a0  = __expf(m0 - mn0);
        const float a1  = __expf(m1 - mn1);
        m0 = mn0; m1 = mn1;

        float rs0 = 0.f, rs1 = 0.f;
#pragma unroll
        for (int j = 0; j < 8; j++) {
            S[j][0] = __expf(S[j][0] - mn0);
            S[j][1] = __expf(S[j][1] - mn0);
            S[j][2] = __expf(S[j][2] - mn1);
            S[j][3] = __expf(S[j][3] - mn1);
            rs0 += S[j][0] + S[j][1];
            rs1 += S[j][2] + S[j][3];
        }
        rs0 += __shfl_xor_sync(0xffffffffu, rs0, 1);
        rs0 += __shfl_xor_sync(0xffffffffu, rs0, 2);
        rs1 += __shfl_xor_sync(0xffffffffu, rs1, 1);
        rs1 += __shfl_xor_sync(0xffffffffu, rs1, 2);
        l0 = l0 * a0 + rs0;
        l1 = l1 * a1 + rs1;

#pragma unroll
        for (int j = 0; j < 8; j++) {
            O[j][0] *= a0; O[j][1] *= a0;
            O[j][2] *= a1; O[j][3] *= a1;
        }

#pragma unroll
        for (int t = 0; t < 4; t++) {
            const uint32_t p0 = pack_h(S[2 * t][0],     S[2 * t][1]);
            const uint32_t p1 = pack_h(S[2 * t][2],     S[2 * t][3]);
            const uint32_t p2 = pack_h(S[2 * t + 1][0], S[2 * t + 1][1]);
            const uint32_t p3 = pack_h(S[2 * t + 1][2], S[2 * t + 1][3]);
#pragma unroll
            for (int j = 0; j < 8; j++) {
                const int lat = 8 * j + g;
                const uint32_t b0 = sV[lat][8 * t + c];
                const uint32_t b1 = sV[lat][8 * t + 4 + c];
                mma_f16(O[j][0], O[j][1], O[j][2], O[j][3], p0, p1, p2, p3, b0, b1);
            }
        }

        if (has_next) {
            __syncthreads();
            store_tile(kvr, vvr);
            __syncthreads();
        }
    }

    const float i0 = 1.f / l0;
    const float i1 = 1.f / l1;
#pragma unroll
    for (int j = 0; j < 8; j++) {
        const int col = 8 * j + 2 * c;
        *reinterpret_cast<uint32_t*>(Yg + base + (size_t)r0 * N_EMBD + col) =
            pack_h(O[j][0] * i0, O[j][1] * i0);
        *reinterpret_cast<uint32_t*>(Yg + base + (size_t)r1 * N_EMBD + col) =
            pack_h(O[j][2] * i1, O[j][3] * i1);
    }
}

// ---------------------------------------------------------------------------
// Launcher. Inputs: x,Wq,bq,Wk,bk,Wv,bv,Wo,bo,Wc   (6 launches)
// ---------------------------------------------------------------------------
extern "C" void kernel_launch(void* const* d_in, const int* in_sizes, int n_in,
                              void* d_out, int out_size)
{
    const float* x  = (const float*)d_in[0];
    const float* Wq = (const float*)d_in[1];
    const float* bq = (const float*)d_in[2];
    const float* Wk = (const float*)d_in[3];
    const float* bk = (const float*)d_in[4];
    const float* Wv = (const float*)d_in[5];
    const float* bv = (const float*)d_in[6];
    const float* Wo = (const float*)d_in[7];
    const float* bo = (const float*)d_in[8];
    const float* Wc = (const float*)d_in[9];
    float* out = (float*)d_out;

    float *pWqc, *pbqc;
    __half *pqkv, *px16, *pys, *pwt;
    cudaGetSymbolAddress((void**)&pWqc, g_Wqc);
    cudaGetSymbolAddress((void**)&pbqc, g_bqc);
    cudaGetSymbolAddress((void**)&pqkv, g_qkv);
    cudaGetSymbolAddress((void**)&px16, g_x);
    cudaGetSymbolAddress((void**)&pys,  g_ys);
    cudaGetSymbolAddress((void**)&pwt,  g_wt);

    const size_t MN = (size_t)MROWS * N_EMBD;

    cudaFuncSetAttribute(gemm_qkv_mma,
                         cudaFuncAttributeMaxDynamicSharedMemorySize, GEMM_SMEM);
    cudaFuncSetAttribute(gemm_out_mma,
                         cudaFuncAttributeMaxDynamicSharedMemorySize, GEMM_SMEM);

    // 1. Wqc build (fp32, coalesced)
    build_wqc<<<4096, 256>>>(Wq, Wc, bq, pWqc, pbqc);

    // 2. convert x to fp16
    const int n2x = MROWS * N_EMBD / 2;
    xcvt<<<(n2x + 255) / 256, 256>>>(x, (__half2*)px16, n2x);

    // 3. transpose all weights to [N][K] fp16 (tiled, coalesced)
    const dim3 tg(N_EMBD / 32, N_EMBD / 32, 4);
    tsplit_all<<<tg, dim3(32, 8)>>>(pWqc, Wk, Wv, Wo, pwt);

    // 4. QKV projection (all single-term fp16)
    const dim3 gq(N_EMBD / 128, MROWS / 128, 3);
    gemm_qkv_mma<<<gq, 256, GEMM_SMEM>>>(px16, pbqc, bk, bv, pqkv);

    // 5. attention
    flash_mma<<<dim3(SEQ / 128, BATCH * N_HEADS), 256>>>(
        pqkv, pqkv + MN, pqkv + 2 * MN, pys);

    // 6. output projection
    const dim3 gg(N_EMBD / 128, MROWS / 128);
    gemm_out_mma<<<gg, 256, GEMM_SMEM>>>(pys, bo, out);
}

// round 17
// speedup vs baseline: 1.7159x; 1.0186x over previous
#include <cuda_runtime.h>
#include <cuda_fp16.h>
#include <cstdint>
#include <cstddef>

// ---------------------------------------------------------------------------
// LatentAttention v14: B=2, T=2048, n_embd=1024, heads=16, latent=64
//   = v13 GEMMs/prep (all single fp16 MMA/step, coalesced prep)
//   + flash: ldmatrix.x4 B-fragments (QK and PV), double-buffered K/V smem
//     (one barrier per key tile).  Arithmetic bit-identical to v13.
// ---------------------------------------------------------------------------

#define N_EMBD   1024
#define N_HEADS  16
#define LATENT   64
#define BATCH    2
#define SEQ      2048
#define MROWS    (BATCH * SEQ)          // 4096
#define KDIM     1024

// ------------------------- device scratch ----------------------------------
__device__ float  g_Wqc[N_EMBD * N_EMBD];
__device__ float  g_bqc[N_EMBD];
__device__ __half g_qkv[3 * MROWS * N_EMBD];    // [qc | k | v] fp16
__device__ __half g_x  [MROWS * N_EMBD];        // x fp16
__device__ __half g_ys [MROWS * N_EMBD];        // y fp16
__device__ __half g_wt[4][N_EMBD * N_EMBD];     // 0=Wqc 1=Wk 2=Wv 3=Wo, [N][K]

// ---------------------------------------------------------------------------
// Wqc[c, h*64+l] = sum_d Wq[c, h*64+d] * Wc[d, l]   (coalesced: col fastest)
// ---------------------------------------------------------------------------
__global__ void build_wqc(const float* __restrict__ Wq,
                          const float* __restrict__ Wc,
                          const float* __restrict__ bq,
                          float* __restrict__ Wqc,
                          float* __restrict__ bqc)
{
    int idx = blockIdx.x * blockDim.x + threadIdx.x;
    int c   = idx >> 10;
    int col = idx & 1023;
    int h   = col >> 6;
    int l   = col & 63;
    const float* wrow = &Wq[(size_t)c * N_EMBD + h * LATENT];
    float s = 0.f;
#pragma unroll 8
    for (int d = 0; d < LATENT; d++)
        s += wrow[d] * Wc[d * LATENT + l];
    Wqc[idx] = s;
    if (c == 0) {
        float sb = 0.f;
#pragma unroll 8
        for (int d = 0; d < LATENT; d++)
            sb += bq[h * LATENT + d] * Wc[d * LATENT + l];
        bqc[col] = sb;
    }
}

// fp32 -> fp16 convert (2 elems / thread)
__global__ void xcvt(const float* __restrict__ src, __half2* __restrict__ dst,
                     int n2)
{
    int i = blockIdx.x * blockDim.x + threadIdx.x;
    if (i >= n2) return;
    const float2 v = reinterpret_cast<const float2*>(src)[i];
    dst[i] = __floats2half2_rn(v.x, v.y);
}

// transpose all 4 weight matrices to [N][K] fp16 (tiled, coalesced)
__global__ void tsplit_all(const float* __restrict__ W0,
                           const float* __restrict__ W1,
                           const float* __restrict__ W2,
                           const float* __restrict__ W3,
                           __half* __restrict__ T)
{
    __shared__ float t[32][33];
    const int z = blockIdx.z;
    const float* W = (z == 0) ? W0 : (z == 1) ? W1 : (z == 2) ? W2 : W3;
    __half* th = T + (size_t)z * N_EMBD * N_EMBD;

    const int tx = threadIdx.x, ty = threadIdx.y;
    const int n0 = blockIdx.x * 32, k0 = blockIdx.y * 32;
#pragma unroll
    for (int i = 0; i < 4; i++)
        t[ty + 8 * i][tx] = W[(size_t)(k0 + ty + 8 * i) * N_EMBD + n0 + tx];
    __syncthreads();
#pragma unroll
    for (int i = 0; i < 4; i++) {
        const int n = n0 + ty + 8 * i;
        const int k = k0 + tx;
        th[(size_t)n * KDIM + k] = __float2half_rn(t[tx][ty + 8 * i]);
    }
}

// ---------------------------------------------------------------------------
// primitives
// ---------------------------------------------------------------------------
__device__ __forceinline__
void mma_f16(float& d0, float& d1, float& d2, float& d3,
             uint32_t a0, uint32_t a1, uint32_t a2, uint32_t a3,
             uint32_t b0, uint32_t b1)
{
    asm volatile(
        "mma.sync.aligned.m16n8k16.row.col.f32.f16.f16.f32 "
        "{%0,%1,%2,%3}, {%4,%5,%6,%7}, {%8,%9}, {%0,%1,%2,%3};\n"
        : "+f"(d0), "+f"(d1), "+f"(d2), "+f"(d3)
        : "r"(a0), "r"(a1), "r"(a2), "r"(a3), "r"(b0), "r"(b1));
}

__device__ __forceinline__ uint32_t pack_h(float x, float y)
{
    __half2 h = __floats2half2_rn(x, y);
    return *reinterpret_cast<uint32_t*>(&h);
}

__device__ __forceinline__ uint32_t mul8h(uint32_t w)
{
    __half2 v = *reinterpret_cast<__half2*>(&w);
    v = __hmul2(v, __floats2half2_rn(0.125f, 0.125f));   // 2^-3 exact
    return *reinterpret_cast<uint32_t*>(&v);
}

__device__ __forceinline__ void cp16(uint32_t d, const void* s) {
    asm volatile("cp.async.cg.shared.global [%0], [%1], 16;" :: "r"(d), "l"(s));
}
__device__ __forceinline__ void cp_commit() {
    asm volatile("cp.async.commit_group;");
}
__device__ __forceinline__ void cp_wait1() {
    asm volatile("cp.async.wait_group 1;");
}
__device__ __forceinline__
void ldsm4(uint32_t& r0, uint32_t& r1, uint32_t& r2, uint32_t& r3, uint32_t a) {
    asm volatile("ldmatrix.sync.aligned.m8n8.x4.shared.b16 {%0,%1,%2,%3}, [%4];"
                 : "=r"(r0), "=r"(r1), "=r"(r2), "=r"(r3) : "r"(a));
}

// ---------------------------------------------------------------------------
// GEMM (single fp16 term): 128x128 tile, BK=32, 8 warps (2m x 4n),
// 3-stage cp.async pipeline (2 arrays/stage), ldmatrix frags.
// ---------------------------------------------------------------------------
#define SMW 20
#define TST (128 * SMW)            // words per array (10240 B)
#define TSTG (2 * TST)             // words per stage (A, B)
#define NST 3
#define GEMM_SMEM (NST * TSTG * 4) // 61440 bytes

template<bool HALF_OUT>
__device__ __forceinline__
void gemm1_body(const __half* __restrict__ A_, const __half* __restrict__ B_,
                const float* __restrict__ bias,
                float* __restrict__ C, __half* __restrict__ Ch,
                int N, int K, int bx, int by)
{
    extern __shared__ uint32_t gsm[];
    const int tid    = threadIdx.x;
    const int lane   = tid & 31;
    const int wid    = tid >> 5;
    const int warp_m = wid >> 2;
    const int warp_n = wid & 3;
    const int m0     = by * 128;
    const int n0     = bx * 128;
    const int lg     = lane >> 2;
    const int lc     = lane & 3;
    const uint32_t sbase = (uint32_t)__cvta_generic_to_shared(gsm);

    float acc[4][4][4];
#pragma unroll
    for (int i = 0; i < 4; i++)
#pragma unroll
        for (int j = 0; j < 4; j++)
#pragma unroll
            for (int c = 0; c < 4; c++) acc[i][j][c] = 0.f;

    const int KT = K >> 5;               // 32

    auto load_stage = [&](int slot, int kb) {
        const uint32_t dst0 = sbase + (uint32_t)(slot * TSTG * 4);
#pragma unroll
        for (int arr = 0; arr < 2; arr++) {
            const __half* src = (arr == 0) ? A_ : B_;
            const int rbase = (arr == 0) ? m0 : n0;
#pragma unroll
            for (int it = 0; it < 2; it++) {
                const int sub = tid + it * 256;      // 0..511
                const int row = sub >> 2;            // 0..127
                const int q   = sub & 3;             // 16B chunk
                cp16(dst0 + (uint32_t)((arr * TST + row * SMW + q * 4) * 4),
                     src + (size_t)(rbase + row) * K + kb + q * 8);
            }
        }
        cp_commit();
    };

    load_stage(0, 0);
    load_stage(1, 32);

    const int arow = lane & 15;
    const int acol = (lane & 16) ? 4 : 0;
    const int brow = (lane & 7) + ((lane & 16) ? 8 : 0);
    const int bcol = (lane & 8) ? 4 : 0;

    for (int kt = 0; kt < KT; kt++) {
        cp_wait1();                       // stage kt resident
        __syncthreads();                  // slot (kt-1)%3 compute finished
        if (kt + 2 < KT) load_stage((kt + 2) % NST, (kt + 2) * 32);
        else             cp_commit();     // keep group accounting exact

        const int slot = kt % NST;
        const uint32_t st   = sbase + (uint32_t)(slot * TSTG * 4);
        const uint32_t offA = st;
        const uint32_t offB = st + TST * 4;

#pragma unroll
        for (int ks = 0; ks < 2; ks++) {
            const int kw = ks * 8;
            uint32_t bh[8];
#pragma unroll
            for (int jp = 0; jp < 2; jp++) {
                const int rB = warp_n * 32 + jp * 16 + brow;
                const uint32_t off = (uint32_t)((rB * SMW + kw + bcol) * 4);
                ldsm4(bh[jp*4+0], bh[jp*4+1], bh[jp*4+2], bh[jp*4+3], offB + off);
            }
#pragma unroll
            for (int i = 0; i < 4; i++) {
                const int rA = warp_m * 64 + i * 16 + arow;
                const uint32_t off = (uint32_t)((rA * SMW + kw + acol) * 4);
                uint32_t a0, a1, a2, a3;
                ldsm4(a0, a1, a2, a3, offA + off);
#pragma unroll
                for (int j = 0; j < 4; j++) {
                    const int bi = (j >> 1) * 4 + (j & 1) * 2;
                    float* d = acc[i][j];
                    mma_f16(d[0], d[1], d[2], d[3],
                            a0, a1, a2, a3, bh[bi], bh[bi+1]);
                }
            }
        }
    }

    // epilogue
#pragma unroll
    for (int j = 0; j < 4; j++) {
        const int cn = n0 + warp_n * 32 + j * 8 + 2 * lc;
        const float2 bb = *reinterpret_cast<const float2*>(&bias[cn]);
#pragma unroll
        for (int i = 0; i < 4; i++) {
            const int r = m0 + warp_m * 64 + i * 16 + lg;
            const float v0 = acc[i][j][0] + bb.x, v1 = acc[i][j][1] + bb.y;
            const float v2 = acc[i][j][2] + bb.x, v3 = acc[i][j][3] + bb.y;
            if (HALF_OUT) {
                *reinterpret_cast<uint32_t*>(Ch + (size_t)r * N + cn) =
                    pack_h(v0, v1);
                *reinterpret_cast<uint32_t*>(Ch + (size_t)(r + 8) * N + cn) =
                    pack_h(v2, v3);
            } else {
                *reinterpret_cast<float2*>(&C[(size_t)r * N + cn]) =
                    make_float2(v0, v1);
                *reinterpret_cast<float2*>(&C[(size_t)(r + 8) * N + cn]) =
                    make_float2(v2, v3);
            }
        }
    }
}

__global__ __launch_bounds__(256, 2)
void gemm_qkv_mma(const __half* __restrict__ x,
                  const float* __restrict__ bqc,
                  const float* __restrict__ bk,
                  const float* __restrict__ bv,
                  __half* __restrict__ qkv)
{
    const int z = blockIdx.z;
    const float* b = (z == 0) ? bqc : (z == 1) ? bk : bv;
    gemm1_body<true>(x, g_wt[z], b, nullptr,
                     qkv + (size_t)z * MROWS * N_EMBD,
                     N_EMBD, KDIM, blockIdx.x, blockIdx.y);
}

__global__ __launch_bounds__(256, 2)
void gemm_out_mma(const __half* __restrict__ y,
                  const float* __restrict__ bo, float* __restrict__ C)
{
    gemm1_body<false>(y, g_wt[3], bo, C, nullptr,
                      N_EMBD, KDIM, blockIdx.x, blockIdx.y);
}

// ---------------------------------------------------------------------------
// Flash attention v14 — single fp16 MMA QK^T/PV; fp32 softmax;
// double-buffered K/V smem (ONE barrier per tile); ldmatrix.x4 B-fragments.
// 256 threads = 8 warps; 128 q-rows (16/warp), 64-key tiles.
// ---------------------------------------------------------------------------
#define FW 36

__global__ __launch_bounds__(256)
void flash_mma(const __half* __restrict__ Qg,
               const __half* __restrict__ Kg, const __half* __restrict__ Vg,
               __half* __restrict__ Yg)
{
    __shared__ uint32_t sK[2][64][FW];   // [buf][key][lat-pair]
    __shared__ uint32_t sV[2][64][FW];   // [buf][lat][key-pair] (transposed)

    const int tid  = threadIdx.x;
    const int lane = tid & 31;
    const int wid  = tid >> 5;
    const int g    = lane >> 2;
    const int c    = lane & 3;
    const int qb   = gridDim.x - 1 - blockIdx.x;   // long blocks first
    const int bh   = blockIdx.y;
    const int b    = bh >> 4;
    const int h    = bh & 15;
    const size_t base = (size_t)b * SEQ * N_EMBD + (size_t)h * LATENT;

    const int r0 = qb * 128 + wid * 16 + g;
    const int r1 = r0 + 8;

    const uint32_t kb0 = (uint32_t)__cvta_generic_to_shared(&sK[0][0][0]);
    const uint32_t vb0 = (uint32_t)__cvta_generic_to_shared(&sV[0][0][0]);

    // ldmatrix lane mapping: 4 matrices = (j, j+1) x (b0, b1)
    const int lrow8 = lane & 7;
    const int lsel  = lane >> 3;                 // 0..3
    const int mrow  = ((lsel & 2) ? 8 : 0) + lrow8;   // row within 16-row pair
    const int mcol  = (lsel & 1) ? 4 : 0;             // word offset b0/b1

    // per-thread load coordinates (4 jobs of 256 threads covering 64x64 tile)
    int lkey[4], lwq[4];
#pragma unroll
    for (int it = 0; it < 4; it++) {
        const int idx = tid + it * 256;
        lkey[it] = idx >> 4;
        lwq[it]  = idx & 15;
    }

    auto store_tile = [&](int buf, const uint2* kvr, const uint2* vvr) {
#pragma unroll
        for (int it = 0; it < 4; it++) {
            *reinterpret_cast<uint2*>(&sK[buf][lkey[it]][lwq[it] * 2]) = kvr[it];
            const __half* ve = reinterpret_cast<const __half*>(&vvr[it]);
            __half* vp = reinterpret_cast<__half*>(&sV[buf][0][0]);
#pragma unroll
            for (int e = 0; e < 4; e++)
                vp[(lwq[it] * 4 + e) * (2 * FW) + lkey[it]] = ve[e];
        }
    };

    // Q fragments (fp16), 1/8 scale folded in (exact power of 2)
    uint32_t qf[4][4];
#pragma unroll
    for (int ks = 0; ks < 4; ks++) {
        const int k0a = 16 * ks + 2 * c;
        const size_t e0 = base + (size_t)r0 * N_EMBD + k0a;
        const size_t e1 = base + (size_t)r1 * N_EMBD + k0a;
        qf[ks][0] = mul8h(*reinterpret_cast<const uint32_t*>(Qg + e0));
        qf[ks][1] = mul8h(*reinterpret_cast<const uint32_t*>(Qg + e1));
        qf[ks][2] = mul8h(*reinterpret_cast<const uint32_t*>(Qg + e0 + 8));
        qf[ks][3] = mul8h(*reinterpret_cast<const uint32_t*>(Qg + e1 + 8));
    }

    // preload tile 0 into buf 0
    {
        uint2 kvr[4], vvr[4];
#pragma unroll
        for (int it = 0; it < 4; it++) {
            const size_t ge = base + (size_t)lkey[it] * N_EMBD + lwq[it] * 4;
            kvr[it] = *reinterpret_cast<const uint2*>(Kg + ge);
            vvr[it] = *reinterpret_cast<const uint2*>(Vg + ge);
        }
        store_tile(0, kvr, vvr);
    }
    __syncthreads();

    float m0 = -1e30f, m1 = -1e30f, l0 = 0.f, l1 = 0.f;
    float O[8][4];
#pragma unroll
    for (int j = 0; j < 8; j++)
#pragma unroll
        for (int t = 0; t < 4; t++) O[j][t] = 0.f;

    const int jmax = 2 * qb + 1;
    for (int jb = 0; jb <= jmax; jb++) {
        const int buf = jb & 1;
        const uint32_t kbb = kb0 + (uint32_t)(buf * 64 * FW * 4);
        const uint32_t vbb = vb0 + (uint32_t)(buf * 64 * FW * 4);

        // prefetch next tile into registers (hidden under compute)
        uint2 kvr[4], vvr[4];
        const bool has_next = (jb < jmax);
        if (has_next) {
#pragma unroll
            for (int it = 0; it < 4; it++) {
                const size_t ge = base +
                    (size_t)((jb + 1) * 64 + lkey[it]) * N_EMBD + lwq[it] * 4;
                kvr[it] = *reinterpret_cast<const uint2*>(Kg + ge);
                vvr[it] = *reinterpret_cast<const uint2*>(Vg + ge);
            }
        }

        // S = Q . K^T (ldmatrix.x4 B-frags: 2 j's per load)
        float S[8][4];
#pragma unroll
        for (int j = 0; j < 8; j++)
#pragma unroll
            for (int t = 0; t < 4; t++) S[j][t] = 0.f;

#pragma unroll
        for (int ks = 0; ks < 4; ks++) {
#pragma unroll
            for (int jp = 0; jp < 4; jp++) {
                const uint32_t a = kbb +
                    (uint32_t)(((16 * jp + mrow) * FW + 8 * ks + mcol) * 4);
                uint32_t b0a, b1a, b0b, b1b;
                ldsm4(b0a, b1a, b0b, b1b, a);
                mma_f16(S[2*jp][0],   S[2*jp][1],   S[2*jp][2],   S[2*jp][3],
                        qf[ks][0], qf[ks][1], qf[ks][2], qf[ks][3], b0a, b1a);
                mma_f16(S[2*jp+1][0], S[2*jp+1][1], S[2*jp+1][2], S[2*jp+1][3],
                        qf[ks][0], qf[ks][1], qf[ks][2], qf[ks][3], b0b, b1b);
            }
        }

        // causal mask
        if (jb >= 2 * qb) {
#pragma unroll
            for (int j = 0; j < 8; j++) {
                const int col = jb * 64 + 8 * j + 2 * c;
                if (col     > r0) S[j][0] = -1e30f;
                if (col + 1 > r0) S[j][1] = -1e30f;
                if (col     > r1) S[j][2] = -1e30f;
                if (col + 1 > r1) S[j][3] = -1e30f;
            }
        }

        // online softmax (fp32)
        float mx0 = -1e30f, mx1 = -1e30f;
#pragma unroll
        for (int j = 0; j < 8; j++) {
            mx0 = fmaxf(mx0, fmaxf(S[j][0], S[j][1]));
            mx1 = fmaxf(mx1, fmaxf(S[j][2], S[j][3]));
        }
        mx0 = fmaxf(mx0, __shfl_xor_sync(0xffffffffu, mx0, 1));
        mx0 = fmaxf(mx0, __shfl_xor_sync(0xffffffffu, mx0, 2));
        mx1 = fmaxf(mx1, __shfl_xor_sync(0xffffffffu, mx1, 1));
        mx1 = fmaxf(mx1, __shfl_xor_sync(0xffffffffu, mx1, 2));

        const float mn0 = fmaxf(m0, mx0);
        const float mn1 = fmaxf(m1, mx1);
        const float a0  = __expf(m0 - mn0);
        const float a1  = __expf(m1 - mn1);
        m0 = mn0; m1 = mn1;

        float rs0 = 0.f, rs1 = 0.f;
#pragma unroll
        for (int j = 0; j < 8; j++) {
            S[j][0] = __expf(S[j][0] - mn0);
            S[j][1] = __expf(S[j][1] - mn0);
            S[j][2] = __expf(S[j][2] - mn1);
            S[j][3] = __expf(S[j][3] - mn1);
            rs0 += S[j][0] + S[j][1];
            rs1 += S[j][2] + S[j][3];
        }
        rs0 += __shfl_xor_sync(0xffffffffu, rs0, 1);
        rs0 += __shfl_xor_sync(0xffffffffu, rs0, 2);
        rs1 += __shfl_xor_sync(0xffffffffu, rs1, 1);
        rs1 += __shfl_xor_sync(0xffffffffu, rs1, 2);
        l0 = l0 * a0 + rs0;
        l1 = l1 * a1 + rs1;

#pragma unroll
        for (int j = 0; j < 8; j++) {
            O[j][0] *= a0; O[j][1] *= a0;
            O[j][2] *= a1; O[j][3] *= a1;
        }

        // O += P . V  (ldmatrix.x4 B-frags from transposed V)
#pragma unroll
        for (int t = 0; t < 4; t++) {
            const uint32_t p0 = pack_h(S[2 * t][0],     S[2 * t][1]);
            const uint32_t p1 = pack_h(S[2 * t][2],     S[2 * t][3]);
            const uint32_t p2 = pack_h(S[2 * t + 1][0], S[2 * t + 1][1]);
            const uint32_t p3 = pack_h(S[2 * t + 1][2], S[2 * t + 1][3]);
#pragma unroll
            for (int jp = 0; jp < 4; jp++) {
                const uint32_t a = vbb +
                    (uint32_t)(((16 * jp + mrow) * FW + 8 * t + mcol) * 4);
                uint32_t b0a, b1a, b0b, b1b;
                ldsm4(b0a, b1a, b0b, b1b, a);
                mma_f16(O[2*jp][0],   O[2*jp][1],   O[2*jp][2],   O[2*jp][3],
                        p0, p1, p2, p3, b0a, b1a);
                mma_f16(O[2*jp+1][0], O[2*jp+1][1], O[2*jp+1][2], O[2*jp+1][3],
                        p0, p1, p2, p3, b0b, b1b);
            }
        }

        if (has_next) {
            store_tile(buf ^ 1, kvr, vvr);   // readers of buf^1 drained at
            __syncthreads();                 // the previous barrier
        }
    }

    // normalize + write y (fp16)
    const float i0 = 1.f / l0;
    const float i1 = 1.f / l1;
#pragma unroll
    for (int j = 0; j < 8; j++) {
        const int col = 8 * j + 2 * c;
        *reinterpret_cast<uint32_t*>(Yg + base + (size_t)r0 * N_EMBD + col) =
            pack_h(O[j][0] * i0, O[j][1] * i0);
        *reinterpret_cast<uint32_t*>(Yg + base + (size_t)r1 * N_EMBD + col) =
            pack_h(O[j][2] * i1, O[j][3] * i1);
    }
}

// ---------------------------------------------------------------------------
// Launcher. Inputs: x,Wq,bq,Wk,bk,Wv,bv,Wo,bo,Wc   (6 launches)
// ---------------------------------------------------------------------------
extern "C" void kernel_launch(void* const* d_in, const int* in_sizes, int n_in,
                              void* d_out, int out_size)
{
    const float* x  = (const float*)d_in[0];
    const float* Wq = (const float*)d_in[1];
    const float* bq = (const float*)d_in[2];
    const float* Wk = (const float*)d_in[3];
    const float* bk = (const float*)d_in[4];
    const float* Wv = (const float*)d_in[5];
    const float* bv = (const float*)d_in[6];
    const float* Wo = (const float*)d_in[7];
    const float* bo = (const float*)d_in[8];
    const float* Wc = (const float*)d_in[9];
    float* out = (float*)d_out;

    float *pWqc, *pbqc;
    __half *pqkv, *px16, *pys, *pwt;
    cudaGetSymbolAddress((void**)&pWqc, g_Wqc);
    cudaGetSymbolAddress((void**)&pbqc, g_bqc);
    cudaGetSymbolAddress((void**)&pqkv, g_qkv);
    cudaGetSymbolAddress((void**)&px16, g_x);
    cudaGetSymbolAddress((void**)&pys,  g_ys);
    cudaGetSymbolAddress((void**)&pwt,  g_wt);

    const size_t MN = (size_t)MROWS * N_EMBD;

    cudaFuncSetAttribute(gemm_qkv_mma,
                         cudaFuncAttributeMaxDynamicSharedMemorySize, GEMM_SMEM);
    cudaFuncSetAttribute(gemm_out_mma,
                         cudaFuncAttributeMaxDynamicSharedMemorySize, GEMM_SMEM);

    // 1. Wqc build (fp32, coalesced)
    build_wqc<<<4096, 256>>>(Wq, Wc, bq, pWqc, pbqc);

    // 2. convert x to fp16
    const int n2x = MROWS * N_EMBD / 2;
    xcvt<<<(n2x + 255) / 256, 256>>>(x, (__half2*)px16, n2x);

    // 3. transpose all weights to [N][K] fp16 (tiled, coalesced)
    const dim3 tg(N_EMBD / 32, N_EMBD / 32, 4);
    tsplit_all<<<tg, dim3(32, 8)>>>(pWqc, Wk, Wv, Wo, pwt);

    // 4. QKV projection (all single-term fp16)
    const dim3 gq(N_EMBD / 128, MROWS / 128, 3);
    gemm_qkv_mma<<<gq, 256, GEMM_SMEM>>>(px16, pbqc, bk, bv, pqkv);

    // 5. attention
    flash_mma<<<dim3(SEQ / 128, BATCH * N_HEADS), 256>>>(
        pqkv, pqkv + MN, pqkv + 2 * MN, pys);

    // 6. output projection
    const dim3 gg(N_EMBD / 128, MROWS / 128);
    gemm_out_mma<<<gg, 256, GEMM_SMEM>>>(pys, bo, out);
}